// round 4
// baseline (speedup 1.0000x reference)
#include <cuda_runtime.h>
#include <cuda_bf16.h>
#include <math.h>

#define N_NODES 131072
#define N_EDGES 65536
#define NB      4096
#define NPG     32
#define ASIZE   53
#define SD      53      /* STATE_DIM */
#define FEAT    117     /* 53 + 64 */
#define XDIM    55
#define XCDIM   289
#define TLEN    50

/* ---------------- scratch (device globals; no allocation allowed) ---------------- */
__device__ float4 g_Tf[660];                       /* gate table fwd: [v][33 (pad)][4 gates] */
__device__ float4 g_Tb[660];
__device__ float4 g_Vf[1024];                      /* W_hh fwd rearranged: [m][lane][4 gates] */
__device__ float4 g_Vb[1024];
__device__ float  g_regex[N_EDGES * 64];
__device__ float  g_in_acc[N_NODES * FEAT];
__device__ float  g_out_acc[N_NODES * FEAT];
__device__ int    g_cnt_in[N_NODES];
__device__ int    g_cnt_out[N_NODES];
__device__ float  g_xc[(size_t)N_NODES * XCDIM];
__device__ float  g_h1[(size_t)N_NODES * 128];
__device__ float  g_h2[(size_t)N_NODES * 64];
__device__ float  g_h3[(size_t)N_NODES * 32];

/* ---------------- helpers ---------------- */
__device__ __forceinline__ float sigf(float x) {
    return __fdividef(1.0f, 1.0f + __expf(-x));
}
__device__ __forceinline__ float tanh_fast(float x) {
    return 2.0f * __fdividef(1.0f, 1.0f + __expf(-2.0f * x)) - 1.0f;
}

/* ---------------- prep: gate tables + W_hh relayout ---------------- */
__global__ void k_prep(const float* __restrict__ emb,
                       const float* __restrict__ wihf, const float* __restrict__ whhf,
                       const float* __restrict__ bf,
                       const float* __restrict__ wihb, const float* __restrict__ whhb,
                       const float* __restrict__ bb)
{
    int tid = blockIdx.x * blockDim.x + threadIdx.x;
    /* T[dir][v][j] = b[j] + sum_k emb[v,k] * w_ih[j,k]; store [v*132 + lane*4 + gate]
       layout: 2 dirs x 20 vocab x 128 gate-units = 5120 threads, 2560 per dir */
    if (tid < 5120) {
        int dir = tid / 2560, r = tid % 2560, v = r >> 7, j = r & 127;
        const float* wih = dir ? wihb : wihf;
        const float* b   = dir ? bb   : bf;
        float s = b[j];
#pragma unroll
        for (int k = 0; k < 8; ++k) s = fmaf(emb[v * 8 + k], wih[j * 8 + k], s);
        int l = j & 31, g = j >> 5;
        ((float*)(dir ? g_Tb : g_Tf))[v * 132 + l * 4 + g] = s;
    }
    /* V[dir][m][lane][gate] = w_hh[gate*32+lane][m]; 2 x 32 x 128 = 8192 exact */
    if (tid < 8192) {
        int dir = tid >> 12, r = tid & 4095, m = r >> 7, j = r & 127;
        int l = j & 31, g = j >> 5;
        const float* whh = dir ? whhb : whhf;
        ((float*)(dir ? g_Vb : g_Vf))[m * 128 + l * 4 + g] = whh[j * 32 + m];
    }
}

/* ---------------- zero accumulators ---------------- */
__global__ void k_zero()
{
    int stride = gridDim.x * blockDim.x;
    int t0 = blockIdx.x * blockDim.x + threadIdx.x;
    for (int i = t0; i < N_NODES * FEAT; i += stride) {
        g_in_acc[i]  = 0.0f;
        g_out_acc[i] = 0.0f;
    }
    for (int i = t0; i < N_NODES; i += stride) {
        g_cnt_in[i]  = 0;
        g_cnt_out[i] = 0;
    }
}

/* ---------------- bidirectional LSTM, warp-per-edge ----------------
   lane l owns h[l], c[l]. 32x128 matvec via 32 shfl broadcasts x 4 FMA. */
__global__ void __launch_bounds__(128) k_lstm(const int* __restrict__ tokens)
{
    __shared__ float4 sV[1024];   /* 16 KB */
    __shared__ float4 sT[660];    /* 10.6 KB */
    int warp = threadIdx.x >> 5, lane = threadIdx.x & 31;
    int e = blockIdx.x * 4 + warp;

    int t0 = tokens[e * TLEN + lane];
    int t1 = (lane < TLEN - 32) ? tokens[e * TLEN + 32 + lane] : 0;

    for (int dir = 0; dir < 2; ++dir) {
        __syncthreads();
        const float4* gV = dir ? g_Vb : g_Vf;
        const float4* gT = dir ? g_Tb : g_Tf;
        for (int i = threadIdx.x; i < 1024; i += 128) sV[i] = gV[i];
        for (int i = threadIdx.x; i < 660;  i += 128) sT[i] = gT[i];
        __syncthreads();

        float h = 0.0f, c = 0.0f, acc = 0.0f;
        for (int t = 0; t < TLEN; ++t) {
            int tt  = dir ? (TLEN - 1 - t) : t;
            int tok = __shfl_sync(0xffffffffu, (tt < 32) ? t0 : t1, tt & 31);
            float4 z4 = sT[tok * 33 + lane];
            float zi = z4.x, zf = z4.y, zg = z4.z, zo = z4.w;
#pragma unroll
            for (int m = 0; m < 32; ++m) {
                float  hm = __shfl_sync(0xffffffffu, h, m);
                float4 w  = sV[m * 32 + lane];
                zi = fmaf(hm, w.x, zi);
                zf = fmaf(hm, w.y, zf);
                zg = fmaf(hm, w.z, zg);
                zo = fmaf(hm, w.w, zo);
            }
            float cn = sigf(zf) * c + sigf(zi) * tanh_fast(zg);
            h = sigf(zo) * tanh_fast(cn);
            c = cn;
            acc += h;
        }
        g_regex[e * 64 + dir * 32 + lane] = acc * (1.0f / TLEN);
    }
}

/* ---------------- edge scatter (segment sums via atomics) ---------------- */
__global__ void __launch_bounds__(128) k_scatter(const int* __restrict__ ei,
                                                 const float* __restrict__ src_num,
                                                 const float* __restrict__ tgt_num)
{
    int e = blockIdx.x;
    int f = threadIdx.x;
    int src = ei[e], tgt = ei[N_EDGES + e];
    if (f == 0) {
        atomicAdd(&g_cnt_out[src], 1);
        atomicAdd(&g_cnt_in[tgt], 1);
    }
    if (f < SD) {
        atomicAdd(&g_out_acc[src * FEAT + f], tgt_num[(size_t)e * SD + f]);
        atomicAdd(&g_in_acc[tgt * FEAT + f],  src_num[(size_t)e * SD + f]);
    } else if (f < FEAT) {
        float rf = g_regex[e * 64 + (f - SD)];
        atomicAdd(&g_out_acc[src * FEAT + f], rf);
        atomicAdd(&g_in_acc[tgt * FEAT + f],  rf);
    }
}

/* ---------------- assemble xc = [x | in_tr | out_tr] ---------------- */
__global__ void k_assemble(const float* __restrict__ x)
{
    int stride = gridDim.x * blockDim.x;
    for (int idx = blockIdx.x * blockDim.x + threadIdx.x; idx < N_NODES * XCDIM; idx += stride) {
        int n = idx / XCDIM, f = idx - n * XCDIM;
        float v;
        if (f < XDIM) {
            v = x[n * XDIM + f];
        } else if (f < XDIM + FEAT) {
            float cnt = fmaxf((float)g_cnt_in[n], 1.0f);
            v = g_in_acc[n * FEAT + (f - XDIM)] / cnt;
        } else {
            float cnt = fmaxf((float)g_cnt_out[n], 1.0f);
            v = g_out_acc[n * FEAT + (f - XDIM - FEAT)] / cnt;
        }
        g_xc[idx] = v;
    }
}

/* ---------------- tiled SGEMM + bias + optional relu ----------------
   C[M,N] = A[M,K] @ B[K,N]; N == BN (single n-block). */
template <int BN, int NT>
__global__ void __launch_bounds__(NT) k_gemm(const float* __restrict__ A,
                                             const float* __restrict__ B,
                                             const float* __restrict__ bias,
                                             float* __restrict__ C,
                                             int M, int N, int K, int doRelu)
{
    constexpr int BM = 128, BK = 16, TM = 8, TN = 8;
    constexpr int NX = BN / TN;
    __shared__ float As[BK][BM + 1];
    __shared__ float Bs[BK][BN];

    int tid = threadIdx.x;
    int tx = tid % NX, ty = tid / NX;
    int bm = blockIdx.x * BM;

    float acc[TM][TN];
#pragma unroll
    for (int i = 0; i < TM; ++i)
#pragma unroll
        for (int j = 0; j < TN; ++j) acc[i][j] = 0.0f;

    int nk = (K + BK - 1) / BK;
    for (int kc = 0; kc < nk; ++kc) {
        int k0 = kc * BK;
        for (int e = tid; e < BM * BK; e += NT) {
            int m = e / BK, k = e % BK;
            As[k][m] = (k0 + k < K) ? A[(bm + m) * K + k0 + k] : 0.0f;
        }
        for (int e = tid * 4; e < BK * BN; e += NT * 4) {
            int k = e / BN, n = e % BN;
            float4 v = make_float4(0.f, 0.f, 0.f, 0.f);
            if (k0 + k < K) v = *(const float4*)(B + (k0 + k) * N + n);
            *(float4*)(&Bs[k][n]) = v;
        }
        __syncthreads();
#pragma unroll
        for (int kk = 0; kk < BK; ++kk) {
            float a[TM], b[TN];
#pragma unroll
            for (int i = 0; i < TM; ++i) a[i] = As[kk][ty * TM + i];
#pragma unroll
            for (int j = 0; j < TN; ++j) b[j] = Bs[kk][tx * TN + j];
#pragma unroll
            for (int i = 0; i < TM; ++i)
#pragma unroll
                for (int j = 0; j < TN; ++j) acc[i][j] = fmaf(a[i], b[j], acc[i][j]);
        }
        __syncthreads();
    }
#pragma unroll
    for (int i = 0; i < TM; ++i) {
        int m = bm + ty * TM + i;
#pragma unroll
        for (int j = 0; j < TN; j += 4) {
            int n = tx * TN + j;
            float4 v;
            v.x = acc[i][j + 0] + bias[n + 0];
            v.y = acc[i][j + 1] + bias[n + 1];
            v.z = acc[i][j + 2] + bias[n + 2];
            v.w = acc[i][j + 3] + bias[n + 3];
            if (doRelu) {
                v.x = fmaxf(v.x, 0.f); v.y = fmaxf(v.y, 0.f);
                v.z = fmaxf(v.z, 0.f); v.w = fmaxf(v.w, 0.f);
            }
            *(float4*)(C + (size_t)m * N + n) = v;
        }
    }
}

/* ---------------- graph mean pool + value head ---------------- */
__global__ void __launch_bounds__(128) k_pool_value(const float* __restrict__ v1w,
                                                    const float* __restrict__ v1b,
                                                    const float* __restrict__ v2w,
                                                    const float* __restrict__ v2b,
                                                    float* __restrict__ out)
{
    __shared__ float s[XCDIM];
    int g = blockIdx.x;
    for (int f = threadIdx.x; f < XCDIM; f += 128) {
        float sum = 0.0f;
        const float* base = g_xc + (size_t)g * NPG * XCDIM + f;
#pragma unroll 4
        for (int i = 0; i < NPG; ++i) sum += base[i * XCDIM];
        s[f] = sum * (1.0f / NPG);
    }
    __syncthreads();
    if (threadIdx.x < 32) {
        int j = threadIdx.x;
        float a = v1b[j];
        for (int i = 0; i < XCDIM; ++i) a = fmaf(s[i], v1w[i * 32 + j], a);
        float hv = fmaxf(a, 0.0f) * v2w[j];
#pragma unroll
        for (int o = 16; o; o >>= 1) hv += __shfl_xor_sync(0xffffffffu, hv, o);
        if (j == 0) out[NB * ASIZE + g] = hv + v2b[0];
    }
}

/* ---------------- pi head (32->1) + ragged pack + log_softmax ---------------- */
__global__ void k_softmax(const float* __restrict__ p4w, const float* __restrict__ p4b,
                          float* __restrict__ out)
{
    int warp = (blockIdx.x * blockDim.x + threadIdx.x) >> 5;
    int lane = threadIdx.x & 31;
    if (warp >= NB) return;
    int node = warp * NPG + lane;

    const float4* h3 = (const float4*)(g_h3 + (size_t)node * 32);
    const float4* w4 = (const float4*)p4w;
    float a = p4b[0];
#pragma unroll
    for (int q = 0; q < 8; ++q) {
        float4 hv = h3[q];
        float4 wv = w4[q];
        a += hv.x * wv.x + hv.y * wv.y + hv.z * wv.z + hv.w * wv.w;
    }

    float m = a;
#pragma unroll
    for (int o = 16; o; o >>= 1) m = fmaxf(m, __shfl_xor_sync(0xffffffffu, m, o));
    m = fmaxf(m, -999.0f);

    float ex = __expf(a - m);
    float ssum = ex;
#pragma unroll
    for (int o = 16; o; o >>= 1) ssum += __shfl_xor_sync(0xffffffffu, ssum, o);
    ssum += (float)(ASIZE - NPG) * __expf(-999.0f - m);
    float lse = __logf(ssum);

    out[warp * ASIZE + lane] = a - m - lse;
    if (lane < ASIZE - 32) out[warp * ASIZE + 32 + lane] = -999.0f - m - lse;
}

/* ---------------- launch ---------------- */
extern "C" void kernel_launch(void* const* d_in, const int* in_sizes, int n_in,
                              void* d_out, int out_size)
{
    const float* x       = (const float*)d_in[0];
    const float* src_num = (const float*)d_in[1];
    const float* tgt_num = (const float*)d_in[2];
    const int*   tokens  = (const int*)d_in[3];
    const int*   ei      = (const int*)d_in[4];
    /* d_in[5] = batch (structure known: i/32), unused */
    const float* emb  = (const float*)d_in[6];
    const float* wihf = (const float*)d_in[7];
    const float* whhf = (const float*)d_in[8];
    const float* bf   = (const float*)d_in[9];
    const float* wihb = (const float*)d_in[10];
    const float* whhb = (const float*)d_in[11];
    const float* bb   = (const float*)d_in[12];
    const float* p1w  = (const float*)d_in[13];
    const float* p1b  = (const float*)d_in[14];
    const float* p2w  = (const float*)d_in[15];
    const float* p2b  = (const float*)d_in[16];
    const float* p3w  = (const float*)d_in[17];
    const float* p3b  = (const float*)d_in[18];
    const float* p4w  = (const float*)d_in[19];
    const float* p4b  = (const float*)d_in[20];
    const float* v1w  = (const float*)d_in[21];
    const float* v1b  = (const float*)d_in[22];
    const float* v2w  = (const float*)d_in[23];
    const float* v2b  = (const float*)d_in[24];
    float* out = (float*)d_out;

    void *pxc = 0, *ph1 = 0, *ph2 = 0, *ph3 = 0;
    cudaGetSymbolAddress(&pxc, g_xc);
    cudaGetSymbolAddress(&ph1, g_h1);
    cudaGetSymbolAddress(&ph2, g_h2);
    cudaGetSymbolAddress(&ph3, g_h3);

    k_prep<<<32, 256>>>(emb, wihf, whhf, bf, wihb, whhb, bb);
    k_zero<<<4096, 256>>>();
    k_lstm<<<N_EDGES / 4, 128>>>(tokens);
    k_scatter<<<N_EDGES, 128>>>(ei, src_num, tgt_num);
    k_assemble<<<8192, 256>>>(x);

    k_gemm<128, 256><<<N_NODES / 128, 256>>>((const float*)pxc, p1w, p1b, (float*)ph1,
                                             N_NODES, 128, XCDIM, 1);
    k_gemm<64, 128><<<N_NODES / 128, 128>>>((const float*)ph1, p2w, p2b, (float*)ph2,
                                            N_NODES, 64, 128, 1);
    k_gemm<32, 64><<<N_NODES / 128, 64>>>((const float*)ph2, p3w, p3b, (float*)ph3,
                                          N_NODES, 32, 64, 1);

    k_pool_value<<<NB, 128>>>(v1w, v1b, v2w, v2b, out);
    k_softmax<<<NB / 8, 256>>>(p4w, p4b, out);
}

// round 5
// speedup vs baseline: 2.8094x; 2.8094x over previous
#include <cuda_runtime.h>
#include <cuda_bf16.h>
#include <math.h>
#include <stdint.h>

#define N_NODES 131072
#define N_EDGES 65536
#define NB      4096
#define NPG     32
#define ASIZE   53
#define SD      53      /* STATE_DIM */
#define FEAT    117     /* 53 + 64 */
#define XDIM    55
#define XCDIM   289
#define TLEN    50

/* ---------------- scratch (device globals; no allocation allowed) ---------------- */
__device__ float4 g_Tf[660];                       /* gate table fwd: [v][33][4 gates i,f,g,o] */
__device__ float4 g_Tb[660];
__device__ float  g_Whi[2][32 * 128];              /* W_hh tf32-hi, col j=(h>>3)*32+g*8+(h&7) */
__device__ float  g_Wlo[2][32 * 128];              /* residual (tf32-rounded) */
__device__ float  g_regex[N_EDGES * 64];
__device__ float  g_in_acc[N_NODES * FEAT];
__device__ float  g_out_acc[N_NODES * FEAT];
__device__ int    g_cnt_in[N_NODES];
__device__ int    g_cnt_out[N_NODES];
__device__ float  g_xc[(size_t)N_NODES * XCDIM];
__device__ float  g_h1[(size_t)N_NODES * 128];
__device__ float  g_h2[(size_t)N_NODES * 64];
__device__ float  g_h3[(size_t)N_NODES * 32];

/* ---------------- helpers ---------------- */
__device__ __forceinline__ float sigf(float x) {
    return __fdividef(1.0f, 1.0f + __expf(-x));
}
__device__ __forceinline__ float tanh_fast(float x) {
    return 2.0f * __fdividef(1.0f, 1.0f + __expf(-2.0f * x)) - 1.0f;
}
__device__ __forceinline__ void tf32_split(float x, uint32_t& hi, uint32_t& lo) {
    uint32_t h;
    asm("cvt.rna.tf32.f32 %0, %1;" : "=r"(h) : "f"(x));
    hi = h;
    lo = __float_as_uint(x - __uint_as_float(h));
}
#define MMA_TF32(D, A, B) \
    asm volatile("mma.sync.aligned.m16n8k8.row.col.f32.tf32.tf32.f32 " \
        "{%0,%1,%2,%3}, {%4,%5,%6,%7}, {%8,%9}, {%0,%1,%2,%3};" \
        : "+f"((D)[0]), "+f"((D)[1]), "+f"((D)[2]), "+f"((D)[3]) \
        : "r"((A)[0]), "r"((A)[1]), "r"((A)[2]), "r"((A)[3]), \
          "r"((B)[0]), "r"((B)[1]))

/* ---------------- prep: gate tables + W_hh tf32 split relayout ---------------- */
__global__ void k_prep(const float* __restrict__ emb,
                       const float* __restrict__ wihf, const float* __restrict__ whhf,
                       const float* __restrict__ bf,
                       const float* __restrict__ wihb, const float* __restrict__ whhb,
                       const float* __restrict__ bb)
{
    int tid = blockIdx.x * blockDim.x + threadIdx.x;
    /* T[dir][v][j] = b[j] + sum_k emb[v,k] * w_ih[j,k]; 2 x 20 x 128 */
    if (tid < 5120) {
        int dir = tid / 2560, r = tid % 2560, v = r >> 7, j = r & 127;
        const float* wih = dir ? wihb : wihf;
        const float* b   = dir ? bb   : bf;
        float s = b[j];
#pragma unroll
        for (int k = 0; k < 8; ++k) s = fmaf(emb[v * 8 + k], wih[j * 8 + k], s);
        int l = j & 31, g = j >> 5;
        ((float*)(dir ? g_Tb : g_Tf))[v * 132 + l * 4 + g] = s;
    }
    /* W relayout: col j = (h>>3)*32 + gate*8 + (h&7); W[m][j] = w_hh[gate*32+h][m] */
    if (tid < 8192) {
        int dir = tid >> 12, r = tid & 4095, m = r >> 7, j = r & 127;
        int wg = j >> 5, g = (j >> 3) & 3, hl = j & 7;
        int h = wg * 8 + hl;
        const float* whh = dir ? whhb : whhf;
        float v = whh[(g * 32 + h) * 32 + m];
        uint32_t hb;
        asm("cvt.rna.tf32.f32 %0, %1;" : "=r"(hb) : "f"(v));
        float hi = __uint_as_float(hb);
        float lof = v - hi;
        uint32_t lb;
        asm("cvt.rna.tf32.f32 %0, %1;" : "=r"(lb) : "f"(lof));
        g_Whi[dir][m * 128 + j] = hi;
        g_Wlo[dir][m * 128 + j] = __uint_as_float(lb);
    }
}

/* ---------------- zero accumulators ---------------- */
__global__ void k_zero()
{
    int stride = gridDim.x * blockDim.x;
    int t0 = blockIdx.x * blockDim.x + threadIdx.x;
    for (int i = t0; i < N_NODES * FEAT; i += stride) {
        g_in_acc[i]  = 0.0f;
        g_out_acc[i] = 0.0f;
    }
    for (int i = t0; i < N_NODES; i += stride) {
        g_cnt_in[i]  = 0;
        g_cnt_out[i] = 0;
    }
}

/* ---------------- bidirectional LSTM via tensor cores ----------------
   Block = 32 edges, 4 warps. Each step: Z[32,128] = T[tok] + H[32,32]@W[32,128]
   with 3x split-tf32 mma (full fp32 accuracy). W lives in B-fragments (regs).
   Warp w owns gate columns [w*32, w*32+32); column layout makes each thread's
   accumulators hold full (i,f,g,o) quads for 8 (edge,hidden) pairs. */
__global__ void __launch_bounds__(128) k_lstm2(const int* __restrict__ tokens)
{
    __shared__ float4 sT[660];          /* token gate table (per dir) */
    __shared__ float  sH[32][36];       /* h state, fp32 */
    __shared__ int    sTok[32 * TLEN];

    int tid = threadIdx.x;
    int w = tid >> 5, lane = tid & 31;
    int q = lane & 3, r = lane >> 2;
    int e0 = blockIdx.x * 32;
    int hcol = w * 8 + 2 * q;           /* this thread's hidden pair base */

    for (int i = tid; i < 32 * TLEN; i += 128) sTok[i] = tokens[e0 * TLEN + i];

    for (int dir = 0; dir < 2; ++dir) {
        __syncthreads();
        const float4* gT = dir ? g_Tb : g_Tf;
        for (int i = tid; i < 660; i += 128) sT[i] = gT[i];
        for (int i = tid; i < 32 * 36; i += 128) ((float*)sH)[i] = 0.0f;

        /* B fragments: [kt][gate][reg], held in registers for the whole pass */
        uint32_t bhi[4][4][2], blo[4][4][2];
        const float* Whi = g_Whi[dir];
        const float* Wlo = g_Wlo[dir];
#pragma unroll
        for (int kt = 0; kt < 4; ++kt)
#pragma unroll
            for (int g = 0; g < 4; ++g) {
                int n = w * 32 + g * 8 + r;
                bhi[kt][g][0] = __float_as_uint(Whi[(kt * 8 + q) * 128 + n]);
                bhi[kt][g][1] = __float_as_uint(Whi[(kt * 8 + q + 4) * 128 + n]);
                blo[kt][g][0] = __float_as_uint(Wlo[(kt * 8 + q) * 128 + n]);
                blo[kt][g][1] = __float_as_uint(Wlo[(kt * 8 + q + 4) * 128 + n]);
            }

        float cst[8], acc[8];
#pragma unroll
        for (int p = 0; p < 8; ++p) { cst[p] = 0.0f; acc[p] = 0.0f; }

        __syncthreads();

        for (int t = 0; t < TLEN; ++t) {
            int tt = dir ? (TLEN - 1 - t) : t;

            /* D init = token gate biases (exact fp32 input contribution) */
            float d[2][4][4];   /* [mt][gate][rh*2+b] */
#pragma unroll
            for (int mt = 0; mt < 2; ++mt)
#pragma unroll
                for (int rh = 0; rh < 2; ++rh) {
                    int edge = mt * 16 + rh * 8 + r;
                    int tk = sTok[edge * TLEN + tt];
                    float4 t0 = sT[tk * 33 + hcol];
                    float4 t1 = sT[tk * 33 + hcol + 1];
                    d[mt][0][rh * 2 + 0] = t0.x; d[mt][1][rh * 2 + 0] = t0.y;
                    d[mt][2][rh * 2 + 0] = t0.z; d[mt][3][rh * 2 + 0] = t0.w;
                    d[mt][0][rh * 2 + 1] = t1.x; d[mt][1][rh * 2 + 1] = t1.y;
                    d[mt][2][rh * 2 + 1] = t1.z; d[mt][3][rh * 2 + 1] = t1.w;
                }

            /* Z += H @ W via 3x split-tf32 mma */
#pragma unroll
            for (int kt = 0; kt < 4; ++kt) {
                uint32_t ahi[2][4], alo[2][4];
#pragma unroll
                for (int mt = 0; mt < 2; ++mt) {
                    float a0 = sH[mt * 16 + r][kt * 8 + q];
                    float a1 = sH[mt * 16 + r + 8][kt * 8 + q];
                    float a2 = sH[mt * 16 + r][kt * 8 + q + 4];
                    float a3 = sH[mt * 16 + r + 8][kt * 8 + q + 4];
                    tf32_split(a0, ahi[mt][0], alo[mt][0]);
                    tf32_split(a1, ahi[mt][1], alo[mt][1]);
                    tf32_split(a2, ahi[mt][2], alo[mt][2]);
                    tf32_split(a3, ahi[mt][3], alo[mt][3]);
                }
#pragma unroll
                for (int mt = 0; mt < 2; ++mt)
#pragma unroll
                    for (int g = 0; g < 4; ++g) {
                        MMA_TF32(d[mt][g], ahi[mt], bhi[kt][g]);
                        MMA_TF32(d[mt][g], alo[mt], bhi[kt][g]);
                        MMA_TF32(d[mt][g], ahi[mt], blo[kt][g]);
                    }
            }
            __syncthreads();   /* all warps finished reading sH */

            /* elementwise gates on registers; write new h */
#pragma unroll
            for (int mt = 0; mt < 2; ++mt)
#pragma unroll
                for (int rh = 0; rh < 2; ++rh)
#pragma unroll
                    for (int b = 0; b < 2; ++b) {
                        int p = mt * 4 + rh * 2 + b;
                        int reg = rh * 2 + b;
                        float zi = d[mt][0][reg], zf = d[mt][1][reg];
                        float zg = d[mt][2][reg], zo = d[mt][3][reg];
                        float cn = sigf(zf) * cst[p] + sigf(zi) * tanh_fast(zg);
                        float h = sigf(zo) * tanh_fast(cn);
                        cst[p] = cn;
                        acc[p] += h;
                        sH[mt * 16 + rh * 8 + r][hcol + b] = h;
                    }
            __syncthreads();
        }

#pragma unroll
        for (int mt = 0; mt < 2; ++mt)
#pragma unroll
            for (int rh = 0; rh < 2; ++rh)
#pragma unroll
                for (int b = 0; b < 2; ++b) {
                    int p = mt * 4 + rh * 2 + b;
                    int edge = e0 + mt * 16 + rh * 8 + r;
                    g_regex[edge * 64 + dir * 32 + hcol + b] = acc[p] * (1.0f / TLEN);
                }
    }
}

/* ---------------- edge scatter (segment sums via atomics) ---------------- */
__global__ void __launch_bounds__(128) k_scatter(const int* __restrict__ ei,
                                                 const float* __restrict__ src_num,
                                                 const float* __restrict__ tgt_num)
{
    int e = blockIdx.x;
    int f = threadIdx.x;
    int src = ei[e], tgt = ei[N_EDGES + e];
    if (f == 0) {
        atomicAdd(&g_cnt_out[src], 1);
        atomicAdd(&g_cnt_in[tgt], 1);
    }
    if (f < SD) {
        atomicAdd(&g_out_acc[src * FEAT + f], tgt_num[(size_t)e * SD + f]);
        atomicAdd(&g_in_acc[tgt * FEAT + f],  src_num[(size_t)e * SD + f]);
    } else if (f < FEAT) {
        float rf = g_regex[e * 64 + (f - SD)];
        atomicAdd(&g_out_acc[src * FEAT + f], rf);
        atomicAdd(&g_in_acc[tgt * FEAT + f],  rf);
    }
}

/* ---------------- assemble xc = [x | in_tr | out_tr] ---------------- */
__global__ void k_assemble(const float* __restrict__ x)
{
    int stride = gridDim.x * blockDim.x;
    for (int idx = blockIdx.x * blockDim.x + threadIdx.x; idx < N_NODES * XCDIM; idx += stride) {
        int n = idx / XCDIM, f = idx - n * XCDIM;
        float v;
        if (f < XDIM) {
            v = x[n * XDIM + f];
        } else if (f < XDIM + FEAT) {
            float cnt = fmaxf((float)g_cnt_in[n], 1.0f);
            v = g_in_acc[n * FEAT + (f - XDIM)] / cnt;
        } else {
            float cnt = fmaxf((float)g_cnt_out[n], 1.0f);
            v = g_out_acc[n * FEAT + (f - XDIM - FEAT)] / cnt;
        }
        g_xc[idx] = v;
    }
}

/* ---------------- tiled SGEMM + bias + optional relu ---------------- */
template <int BN, int NT>
__global__ void __launch_bounds__(NT) k_gemm(const float* __restrict__ A,
                                             const float* __restrict__ B,
                                             const float* __restrict__ bias,
                                             float* __restrict__ C,
                                             int M, int N, int K, int doRelu)
{
    constexpr int BM = 128, BK = 16, TM = 8, TN = 8;
    constexpr int NX = BN / TN;
    __shared__ float As[BK][BM + 1];
    __shared__ float Bs[BK][BN];

    int tid = threadIdx.x;
    int tx = tid % NX, ty = tid / NX;
    int bm = blockIdx.x * BM;

    float acc[TM][TN];
#pragma unroll
    for (int i = 0; i < TM; ++i)
#pragma unroll
        for (int j = 0; j < TN; ++j) acc[i][j] = 0.0f;

    int nk = (K + BK - 1) / BK;
    for (int kc = 0; kc < nk; ++kc) {
        int k0 = kc * BK;
        for (int e = tid; e < BM * BK; e += NT) {
            int m = e / BK, k = e % BK;
            As[k][m] = (k0 + k < K) ? A[(bm + m) * K + k0 + k] : 0.0f;
        }
        for (int e = tid * 4; e < BK * BN; e += NT * 4) {
            int k = e / BN, n = e % BN;
            float4 v = make_float4(0.f, 0.f, 0.f, 0.f);
            if (k0 + k < K) v = *(const float4*)(B + (k0 + k) * N + n);
            *(float4*)(&Bs[k][n]) = v;
        }
        __syncthreads();
#pragma unroll
        for (int kk = 0; kk < BK; ++kk) {
            float a[TM], b[TN];
#pragma unroll
            for (int i = 0; i < TM; ++i) a[i] = As[kk][ty * TM + i];
#pragma unroll
            for (int j = 0; j < TN; ++j) b[j] = Bs[kk][tx * TN + j];
#pragma unroll
            for (int i = 0; i < TM; ++i)
#pragma unroll
                for (int j = 0; j < TN; ++j) acc[i][j] = fmaf(a[i], b[j], acc[i][j]);
        }
        __syncthreads();
    }
#pragma unroll
    for (int i = 0; i < TM; ++i) {
        int m = bm + ty * TM + i;
#pragma unroll
        for (int j = 0; j < TN; j += 4) {
            int n = tx * TN + j;
            float4 v;
            v.x = acc[i][j + 0] + bias[n + 0];
            v.y = acc[i][j + 1] + bias[n + 1];
            v.z = acc[i][j + 2] + bias[n + 2];
            v.w = acc[i][j + 3] + bias[n + 3];
            if (doRelu) {
                v.x = fmaxf(v.x, 0.f); v.y = fmaxf(v.y, 0.f);
                v.z = fmaxf(v.z, 0.f); v.w = fmaxf(v.w, 0.f);
            }
            *(float4*)(C + (size_t)m * N + n) = v;
        }
    }
}

/* ---------------- graph mean pool + value head ---------------- */
__global__ void __launch_bounds__(128) k_pool_value(const float* __restrict__ v1w,
                                                    const float* __restrict__ v1b,
                                                    const float* __restrict__ v2w,
                                                    const float* __restrict__ v2b,
                                                    float* __restrict__ out)
{
    __shared__ float s[XCDIM];
    int g = blockIdx.x;
    for (int f = threadIdx.x; f < XCDIM; f += 128) {
        float sum = 0.0f;
        const float* base = g_xc + (size_t)g * NPG * XCDIM + f;
#pragma unroll 4
        for (int i = 0; i < NPG; ++i) sum += base[i * XCDIM];
        s[f] = sum * (1.0f / NPG);
    }
    __syncthreads();
    if (threadIdx.x < 32) {
        int j = threadIdx.x;
        float a = v1b[j];
        for (int i = 0; i < XCDIM; ++i) a = fmaf(s[i], v1w[i * 32 + j], a);
        float hv = fmaxf(a, 0.0f) * v2w[j];
#pragma unroll
        for (int o = 16; o; o >>= 1) hv += __shfl_xor_sync(0xffffffffu, hv, o);
        if (j == 0) out[NB * ASIZE + g] = hv + v2b[0];
    }
}

/* ---------------- pi head (32->1) + ragged pack + log_softmax ---------------- */
__global__ void k_softmax(const float* __restrict__ p4w, const float* __restrict__ p4b,
                          float* __restrict__ out)
{
    int warp = (blockIdx.x * blockDim.x + threadIdx.x) >> 5;
    int lane = threadIdx.x & 31;
    if (warp >= NB) return;
    int node = warp * NPG + lane;

    const float4* h3 = (const float4*)(g_h3 + (size_t)node * 32);
    const float4* w4 = (const float4*)p4w;
    float a = p4b[0];
#pragma unroll
    for (int qq = 0; qq < 8; ++qq) {
        float4 hv = h3[qq];
        float4 wv = w4[qq];
        a += hv.x * wv.x + hv.y * wv.y + hv.z * wv.z + hv.w * wv.w;
    }

    float m = a;
#pragma unroll
    for (int o = 16; o; o >>= 1) m = fmaxf(m, __shfl_xor_sync(0xffffffffu, m, o));
    m = fmaxf(m, -999.0f);

    float ex = __expf(a - m);
    float ssum = ex;
#pragma unroll
    for (int o = 16; o; o >>= 1) ssum += __shfl_xor_sync(0xffffffffu, ssum, o);
    ssum += (float)(ASIZE - NPG) * __expf(-999.0f - m);
    float lse = __logf(ssum);

    out[warp * ASIZE + lane] = a - m - lse;
    if (lane < ASIZE - 32) out[warp * ASIZE + 32 + lane] = -999.0f - m - lse;
}

/* ---------------- launch ---------------- */
extern "C" void kernel_launch(void* const* d_in, const int* in_sizes, int n_in,
                              void* d_out, int out_size)
{
    const float* x       = (const float*)d_in[0];
    const float* src_num = (const float*)d_in[1];
    const float* tgt_num = (const float*)d_in[2];
    const int*   tokens  = (const int*)d_in[3];
    const int*   ei      = (const int*)d_in[4];
    /* d_in[5] = batch (structure known: i/32), unused */
    const float* emb  = (const float*)d_in[6];
    const float* wihf = (const float*)d_in[7];
    const float* whhf = (const float*)d_in[8];
    const float* bf   = (const float*)d_in[9];
    const float* wihb = (const float*)d_in[10];
    const float* whhb = (const float*)d_in[11];
    const float* bb   = (const float*)d_in[12];
    const float* p1w  = (const float*)d_in[13];
    const float* p1b  = (const float*)d_in[14];
    const float* p2w  = (const float*)d_in[15];
    const float* p2b  = (const float*)d_in[16];
    const float* p3w  = (const float*)d_in[17];
    const float* p3b  = (const float*)d_in[18];
    const float* p4w  = (const float*)d_in[19];
    const float* p4b  = (const float*)d_in[20];
    const float* v1w  = (const float*)d_in[21];
    const float* v1b  = (const float*)d_in[22];
    const float* v2w  = (const float*)d_in[23];
    const float* v2b  = (const float*)d_in[24];
    float* out = (float*)d_out;

    void *pxc = 0, *ph1 = 0, *ph2 = 0, *ph3 = 0;
    cudaGetSymbolAddress(&pxc, g_xc);
    cudaGetSymbolAddress(&ph1, g_h1);
    cudaGetSymbolAddress(&ph2, g_h2);
    cudaGetSymbolAddress(&ph3, g_h3);

    k_prep<<<32, 256>>>(emb, wihf, whhf, bf, wihb, whhb, bb);
    k_zero<<<4096, 256>>>();
    k_lstm2<<<N_EDGES / 32, 128>>>(tokens);
    k_scatter<<<N_EDGES, 128>>>(ei, src_num, tgt_num);
    k_assemble<<<8192, 256>>>(x);

    k_gemm<128, 256><<<N_NODES / 128, 256>>>((const float*)pxc, p1w, p1b, (float*)ph1,
                                             N_NODES, 128, XCDIM, 1);
    k_gemm<64, 128><<<N_NODES / 128, 128>>>((const float*)ph1, p2w, p2b, (float*)ph2,
                                            N_NODES, 64, 128, 1);
    k_gemm<32, 64><<<N_NODES / 128, 64>>>((const float*)ph2, p3w, p3b, (float*)ph3,
                                          N_NODES, 32, 64, 1);

    k_pool_value<<<NB, 128>>>(v1w, v1b, v2w, v2b, out);
    k_softmax<<<NB / 8, 256>>>(p4w, p4b, out);
}

// round 6
// speedup vs baseline: 2.8440x; 1.0123x over previous
#include <cuda_runtime.h>
#include <cuda_bf16.h>
#include <math.h>
#include <stdint.h>

#define N_NODES 131072
#define N_EDGES 65536
#define NB      4096
#define NPG     32
#define ASIZE   53
#define SD      53      /* STATE_DIM */
#define FEAT    117     /* 53 + 64 */
#define XDIM    55
#define XCDIM   289
#define TLEN    50

/* ---------------- scratch (device globals; no allocation allowed) ---------------- */
__device__ float4 g_Tf[660];                       /* gate table fwd: [v][33][4 gates i,f,g,o] */
__device__ float4 g_Tb[660];
__device__ float  g_Whi[2][32 * 128];              /* W_hh tf32-hi, col j=(h>>3)*32+g*8+(h&7) */
__device__ float  g_Wlo[2][32 * 128];              /* residual (tf32-rounded) */
__device__ float  g_regex[N_EDGES * 64];
__device__ float  g_in_acc[N_NODES * FEAT];
__device__ float  g_out_acc[N_NODES * FEAT];
__device__ int    g_cnt_in[N_NODES];
__device__ int    g_cnt_out[N_NODES];
__device__ float  g_inv_in[N_NODES];
__device__ float  g_inv_out[N_NODES];
__device__ float  g_h1[(size_t)N_NODES * 128];
__device__ float  g_h2[(size_t)N_NODES * 64];
__device__ float  g_h3[(size_t)N_NODES * 32];

/* ---------------- helpers ---------------- */
__device__ __forceinline__ float tanhh(float x) {
    float y;
    asm("tanh.approx.f32 %0, %1;" : "=f"(y) : "f"(x));
    return y;
}
__device__ __forceinline__ float sigf(float x) {
    return fmaf(0.5f, tanhh(0.5f * x), 0.5f);
}
__device__ __forceinline__ void tf32_split(float x, uint32_t& hi, uint32_t& lo) {
    uint32_t h;
    asm("cvt.rna.tf32.f32 %0, %1;" : "=r"(h) : "f"(x));
    hi = h;
    lo = __float_as_uint(x - __uint_as_float(h));
}
#define MMA_TF32(D, A, B) \
    asm volatile("mma.sync.aligned.m16n8k8.row.col.f32.tf32.tf32.f32 " \
        "{%0,%1,%2,%3}, {%4,%5,%6,%7}, {%8,%9}, {%0,%1,%2,%3};" \
        : "+f"((D)[0]), "+f"((D)[1]), "+f"((D)[2]), "+f"((D)[3]) \
        : "r"((A)[0]), "r"((A)[1]), "r"((A)[2]), "r"((A)[3]), \
          "r"((B)[0]), "r"((B)[1]))

/* fused xc element: [x | in_acc*inv | out_acc*inv] */
__device__ __forceinline__ float xc_elem(const float* __restrict__ x, int n, int f) {
    if (f < XDIM)        return x[n * XDIM + f];
    if (f < XDIM + FEAT) return g_in_acc[n * FEAT + (f - XDIM)] * g_inv_in[n];
    if (f < XCDIM)       return g_out_acc[n * FEAT + (f - XDIM - FEAT)] * g_inv_out[n];
    return 0.0f;
}

/* ---------------- prep: gate tables + W_hh tf32 split relayout ---------------- */
__global__ void k_prep(const float* __restrict__ emb,
                       const float* __restrict__ wihf, const float* __restrict__ whhf,
                       const float* __restrict__ bf,
                       const float* __restrict__ wihb, const float* __restrict__ whhb,
                       const float* __restrict__ bb)
{
    int tid = blockIdx.x * blockDim.x + threadIdx.x;
    /* T[dir][v][j] = b[j] + sum_k emb[v,k] * w_ih[j,k]; 2 x 20 x 128 */
    if (tid < 5120) {
        int dir = tid / 2560, r = tid % 2560, v = r >> 7, j = r & 127;
        const float* wih = dir ? wihb : wihf;
        const float* b   = dir ? bb   : bf;
        float s = b[j];
#pragma unroll
        for (int k = 0; k < 8; ++k) s = fmaf(emb[v * 8 + k], wih[j * 8 + k], s);
        int l = j & 31, g = j >> 5;
        ((float*)(dir ? g_Tb : g_Tf))[v * 132 + l * 4 + g] = s;
    }
    /* W relayout: col j = (h>>3)*32 + gate*8 + (h&7); W[m][j] = w_hh[gate*32+h][m] */
    if (tid < 8192) {
        int dir = tid >> 12, r = tid & 4095, m = r >> 7, j = r & 127;
        int wg = j >> 5, g = (j >> 3) & 3, hl = j & 7;
        int h = wg * 8 + hl;
        const float* whh = dir ? whhb : whhf;
        float v = whh[(g * 32 + h) * 32 + m];
        uint32_t hb;
        asm("cvt.rna.tf32.f32 %0, %1;" : "=r"(hb) : "f"(v));
        float hi = __uint_as_float(hb);
        float lof = v - hi;
        uint32_t lb;
        asm("cvt.rna.tf32.f32 %0, %1;" : "=r"(lb) : "f"(lof));
        g_Whi[dir][m * 128 + j] = hi;
        g_Wlo[dir][m * 128 + j] = __uint_as_float(lb);
    }
}

/* ---------------- zero accumulators ---------------- */
__global__ void k_zero()
{
    int stride = gridDim.x * blockDim.x;
    int t0 = blockIdx.x * blockDim.x + threadIdx.x;
    for (int i = t0; i < N_NODES * FEAT; i += stride) {
        g_in_acc[i]  = 0.0f;
        g_out_acc[i] = 0.0f;
    }
    for (int i = t0; i < N_NODES; i += stride) {
        g_cnt_in[i]  = 0;
        g_cnt_out[i] = 0;
    }
}

/* ---------------- reciprocal counts (after scatter) ---------------- */
__global__ void k_inv()
{
    int n = blockIdx.x * blockDim.x + threadIdx.x;
    if (n < N_NODES) {
        g_inv_in[n]  = 1.0f / fmaxf((float)g_cnt_in[n], 1.0f);
        g_inv_out[n] = 1.0f / fmaxf((float)g_cnt_out[n], 1.0f);
    }
}

/* ---------------- bidirectional LSTM via tensor cores ----------------
   Block = 32 edges, 4 warps. Each step: Z[32,128] = T[tok] + H[32,32]@W[32,128]
   with 3x split-tf32 mma. W lives in B-fragments (regs). Double-buffered H,
   one barrier per step. Activations use HW tanh.approx. */
__global__ void __launch_bounds__(128) k_lstm2(const int* __restrict__ tokens)
{
    __shared__ float4 sT[660];          /* token gate table (per dir) */
    __shared__ float  sH[2][32][36];    /* h state, double-buffered */
    __shared__ int    sTok[32 * TLEN];

    int tid = threadIdx.x;
    int w = tid >> 5, lane = tid & 31;
    int q = lane & 3, r = lane >> 2;
    int e0 = blockIdx.x * 32;
    int hcol = w * 8 + 2 * q;           /* this thread's hidden pair base */

    for (int i = tid; i < 32 * TLEN; i += 128) sTok[i] = tokens[e0 * TLEN + i];

    for (int dir = 0; dir < 2; ++dir) {
        __syncthreads();
        const float4* gT = dir ? g_Tb : g_Tf;
        for (int i = tid; i < 660; i += 128) sT[i] = gT[i];
        for (int i = tid; i < 2 * 32 * 36; i += 128) ((float*)sH)[i] = 0.0f;

        /* B fragments: [kt][gate][reg], held in registers for the whole pass */
        uint32_t bhi[4][4][2], blo[4][4][2];
        const float* Whi = g_Whi[dir];
        const float* Wlo = g_Wlo[dir];
#pragma unroll
        for (int kt = 0; kt < 4; ++kt)
#pragma unroll
            for (int g = 0; g < 4; ++g) {
                int n = w * 32 + g * 8 + r;
                bhi[kt][g][0] = __float_as_uint(Whi[(kt * 8 + q) * 128 + n]);
                bhi[kt][g][1] = __float_as_uint(Whi[(kt * 8 + q + 4) * 128 + n]);
                blo[kt][g][0] = __float_as_uint(Wlo[(kt * 8 + q) * 128 + n]);
                blo[kt][g][1] = __float_as_uint(Wlo[(kt * 8 + q + 4) * 128 + n]);
            }

        float cst[8], acc[8];
#pragma unroll
        for (int p = 0; p < 8; ++p) { cst[p] = 0.0f; acc[p] = 0.0f; }

        __syncthreads();

        int pb = 0;
        for (int t = 0; t < TLEN; ++t) {
            int tt = dir ? (TLEN - 1 - t) : t;

            /* D init = token gate biases (exact fp32 input contribution) */
            float d[2][4][4];   /* [mt][gate][rh*2+b] */
#pragma unroll
            for (int mt = 0; mt < 2; ++mt)
#pragma unroll
                for (int rh = 0; rh < 2; ++rh) {
                    int edge = mt * 16 + rh * 8 + r;
                    int tk = sTok[edge * TLEN + tt];
                    float4 t0 = sT[tk * 33 + hcol];
                    float4 t1 = sT[tk * 33 + hcol + 1];
                    d[mt][0][rh * 2 + 0] = t0.x; d[mt][1][rh * 2 + 0] = t0.y;
                    d[mt][2][rh * 2 + 0] = t0.z; d[mt][3][rh * 2 + 0] = t0.w;
                    d[mt][0][rh * 2 + 1] = t1.x; d[mt][1][rh * 2 + 1] = t1.y;
                    d[mt][2][rh * 2 + 1] = t1.z; d[mt][3][rh * 2 + 1] = t1.w;
                }

            /* Z += H @ W via 3x split-tf32 mma */
#pragma unroll
            for (int kt = 0; kt < 4; ++kt) {
                uint32_t ahi[2][4], alo[2][4];
#pragma unroll
                for (int mt = 0; mt < 2; ++mt) {
                    float a0 = sH[pb][mt * 16 + r][kt * 8 + q];
                    float a1 = sH[pb][mt * 16 + r + 8][kt * 8 + q];
                    float a2 = sH[pb][mt * 16 + r][kt * 8 + q + 4];
                    float a3 = sH[pb][mt * 16 + r + 8][kt * 8 + q + 4];
                    tf32_split(a0, ahi[mt][0], alo[mt][0]);
                    tf32_split(a1, ahi[mt][1], alo[mt][1]);
                    tf32_split(a2, ahi[mt][2], alo[mt][2]);
                    tf32_split(a3, ahi[mt][3], alo[mt][3]);
                }
#pragma unroll
                for (int mt = 0; mt < 2; ++mt)
#pragma unroll
                    for (int g = 0; g < 4; ++g) {
                        MMA_TF32(d[mt][g], ahi[mt], bhi[kt][g]);
                        MMA_TF32(d[mt][g], alo[mt], bhi[kt][g]);
                        MMA_TF32(d[mt][g], ahi[mt], blo[kt][g]);
                    }
            }

            /* elementwise gates on registers; write new h into other buffer */
#pragma unroll
            for (int mt = 0; mt < 2; ++mt)
#pragma unroll
                for (int rh = 0; rh < 2; ++rh)
#pragma unroll
                    for (int b = 0; b < 2; ++b) {
                        int p = mt * 4 + rh * 2 + b;
                        int reg = rh * 2 + b;
                        float zi = d[mt][0][reg], zf = d[mt][1][reg];
                        float zg = d[mt][2][reg], zo = d[mt][3][reg];
                        float cn = sigf(zf) * cst[p] + sigf(zi) * tanhh(zg);
                        float h = sigf(zo) * tanhh(cn);
                        cst[p] = cn;
                        acc[p] += h;
                        sH[pb ^ 1][mt * 16 + rh * 8 + r][hcol + b] = h;
                    }
            __syncthreads();
            pb ^= 1;
        }

#pragma unroll
        for (int mt = 0; mt < 2; ++mt)
#pragma unroll
            for (int rh = 0; rh < 2; ++rh)
#pragma unroll
                for (int b = 0; b < 2; ++b) {
                    int p = mt * 4 + rh * 2 + b;
                    int edge = e0 + mt * 16 + rh * 8 + r;
                    g_regex[edge * 64 + dir * 32 + hcol + b] = acc[p] * (1.0f / TLEN);
                }
    }
}

/* ---------------- edge scatter (segment sums via atomics) ---------------- */
__global__ void __launch_bounds__(128) k_scatter(const int* __restrict__ ei,
                                                 const float* __restrict__ src_num,
                                                 const float* __restrict__ tgt_num)
{
    int e = blockIdx.x;
    int f = threadIdx.x;
    int src = ei[e], tgt = ei[N_EDGES + e];
    if (f == 0) {
        atomicAdd(&g_cnt_out[src], 1);
        atomicAdd(&g_cnt_in[tgt], 1);
    }
    if (f < SD) {
        atomicAdd(&g_out_acc[src * FEAT + f], tgt_num[(size_t)e * SD + f]);
        atomicAdd(&g_in_acc[tgt * FEAT + f],  src_num[(size_t)e * SD + f]);
    } else if (f < FEAT) {
        float rf = g_regex[e * 64 + (f - SD)];
        atomicAdd(&g_out_acc[src * FEAT + f], rf);
        atomicAdd(&g_in_acc[tgt * FEAT + f],  rf);
    }
}

/* ---------------- gemm1: fused-A SGEMM  C = relu(xc @ p1w + b) ---------------- */
__global__ void __launch_bounds__(256) k_gemm1(const float* __restrict__ x,
                                               const float* __restrict__ B,
                                               const float* __restrict__ bias,
                                               float* __restrict__ C)
{
    constexpr int BM = 128, BN = 128, BK = 16, TM = 8, TN = 8, NT = 256;
    constexpr int NX = BN / TN;
    constexpr int K = XCDIM, N = BN;
    __shared__ float As[BK][BM + 1];
    __shared__ float Bs[BK][BN];

    int tid = threadIdx.x;
    int tx = tid % NX, ty = tid / NX;
    int bm = blockIdx.x * BM;

    float acc[TM][TN];
#pragma unroll
    for (int i = 0; i < TM; ++i)
#pragma unroll
        for (int j = 0; j < TN; ++j) acc[i][j] = 0.0f;

    int nk = (K + BK - 1) / BK;
    for (int kc = 0; kc < nk; ++kc) {
        int k0 = kc * BK;
        for (int e = tid; e < BM * BK; e += NT) {
            int m = e / BK, k = e % BK;
            As[k][m] = xc_elem(x, bm + m, k0 + k);
        }
        for (int e = tid * 4; e < BK * BN; e += NT * 4) {
            int k = e / BN, n = e % BN;
            float4 v = make_float4(0.f, 0.f, 0.f, 0.f);
            if (k0 + k < K) v = *(const float4*)(B + (k0 + k) * N + n);
            *(float4*)(&Bs[k][n]) = v;
        }
        __syncthreads();
#pragma unroll
        for (int kk = 0; kk < BK; ++kk) {
            float a[TM], b[TN];
#pragma unroll
            for (int i = 0; i < TM; ++i) a[i] = As[kk][ty * TM + i];
#pragma unroll
            for (int j = 0; j < TN; ++j) b[j] = Bs[kk][tx * TN + j];
#pragma unroll
            for (int i = 0; i < TM; ++i)
#pragma unroll
                for (int j = 0; j < TN; ++j) acc[i][j] = fmaf(a[i], b[j], acc[i][j]);
        }
        __syncthreads();
    }
#pragma unroll
    for (int i = 0; i < TM; ++i) {
        int m = bm + ty * TM + i;
#pragma unroll
        for (int j = 0; j < TN; j += 4) {
            int n = tx * TN + j;
            float4 v;
            v.x = fmaxf(acc[i][j + 0] + bias[n + 0], 0.f);
            v.y = fmaxf(acc[i][j + 1] + bias[n + 1], 0.f);
            v.z = fmaxf(acc[i][j + 2] + bias[n + 2], 0.f);
            v.w = fmaxf(acc[i][j + 3] + bias[n + 3], 0.f);
            *(float4*)(C + (size_t)m * N + n) = v;
        }
    }
}

/* ---------------- tiled SGEMM + bias + relu (gemm2/3) ---------------- */
template <int BN, int NT>
__global__ void __launch_bounds__(NT) k_gemm(const float* __restrict__ A,
                                             const float* __restrict__ B,
                                             const float* __restrict__ bias,
                                             float* __restrict__ C,
                                             int M, int N, int K, int doRelu)
{
    constexpr int BM = 128, BK = 16, TM = 8, TN = 8;
    constexpr int NX = BN / TN;
    __shared__ float As[BK][BM + 1];
    __shared__ float Bs[BK][BN];

    int tid = threadIdx.x;
    int tx = tid % NX, ty = tid / NX;
    int bm = blockIdx.x * BM;

    float acc[TM][TN];
#pragma unroll
    for (int i = 0; i < TM; ++i)
#pragma unroll
        for (int j = 0; j < TN; ++j) acc[i][j] = 0.0f;

    int nk = (K + BK - 1) / BK;
    for (int kc = 0; kc < nk; ++kc) {
        int k0 = kc * BK;
        for (int e = tid; e < BM * BK; e += NT) {
            int m = e / BK, k = e % BK;
            As[k][m] = (k0 + k < K) ? A[(bm + m) * K + k0 + k] : 0.0f;
        }
        for (int e = tid * 4; e < BK * BN; e += NT * 4) {
            int k = e / BN, n = e % BN;
            float4 v = make_float4(0.f, 0.f, 0.f, 0.f);
            if (k0 + k < K) v = *(const float4*)(B + (k0 + k) * N + n);
            *(float4*)(&Bs[k][n]) = v;
        }
        __syncthreads();
#pragma unroll
        for (int kk = 0; kk < BK; ++kk) {
            float a[TM], b[TN];
#pragma unroll
            for (int i = 0; i < TM; ++i) a[i] = As[kk][ty * TM + i];
#pragma unroll
            for (int j = 0; j < TN; ++j) b[j] = Bs[kk][tx * TN + j];
#pragma unroll
            for (int i = 0; i < TM; ++i)
#pragma unroll
                for (int j = 0; j < TN; ++j) acc[i][j] = fmaf(a[i], b[j], acc[i][j]);
        }
        __syncthreads();
    }
#pragma unroll
    for (int i = 0; i < TM; ++i) {
        int m = bm + ty * TM + i;
#pragma unroll
        for (int j = 0; j < TN; j += 4) {
            int n = tx * TN + j;
            float4 v;
            v.x = acc[i][j + 0] + bias[n + 0];
            v.y = acc[i][j + 1] + bias[n + 1];
            v.z = acc[i][j + 2] + bias[n + 2];
            v.w = acc[i][j + 3] + bias[n + 3];
            if (doRelu) {
                v.x = fmaxf(v.x, 0.f); v.y = fmaxf(v.y, 0.f);
                v.z = fmaxf(v.z, 0.f); v.w = fmaxf(v.w, 0.f);
            }
            *(float4*)(C + (size_t)m * N + n) = v;
        }
    }
}

/* ---------------- graph mean pool + value head (fused xc) ---------------- */
__global__ void __launch_bounds__(128) k_pool_value(const float* __restrict__ x,
                                                    const float* __restrict__ v1w,
                                                    const float* __restrict__ v1b,
                                                    const float* __restrict__ v2w,
                                                    const float* __restrict__ v2b,
                                                    float* __restrict__ out)
{
    __shared__ float s[XCDIM];
    int g = blockIdx.x;
    for (int f = threadIdx.x; f < XCDIM; f += 128) {
        float sum = 0.0f;
#pragma unroll 4
        for (int i = 0; i < NPG; ++i) sum += xc_elem(x, g * NPG + i, f);
        s[f] = sum * (1.0f / NPG);
    }
    __syncthreads();
    if (threadIdx.x < 32) {
        int j = threadIdx.x;
        float a = v1b[j];
        for (int i = 0; i < XCDIM; ++i) a = fmaf(s[i], v1w[i * 32 + j], a);
        float hv = fmaxf(a, 0.0f) * v2w[j];
#pragma unroll
        for (int o = 16; o; o >>= 1) hv += __shfl_xor_sync(0xffffffffu, hv, o);
        if (j == 0) out[NB * ASIZE + g] = hv + v2b[0];
    }
}

/* ---------------- pi head (32->1) + ragged pack + log_softmax ---------------- */
__global__ void k_softmax(const float* __restrict__ p4w, const float* __restrict__ p4b,
                          float* __restrict__ out)
{
    int warp = (blockIdx.x * blockDim.x + threadIdx.x) >> 5;
    int lane = threadIdx.x & 31;
    if (warp >= NB) return;
    int node = warp * NPG + lane;

    const float4* h3 = (const float4*)(g_h3 + (size_t)node * 32);
    const float4* w4 = (const float4*)p4w;
    float a = p4b[0];
#pragma unroll
    for (int qq = 0; qq < 8; ++qq) {
        float4 hv = h3[qq];
        float4 wv = w4[qq];
        a += hv.x * wv.x + hv.y * wv.y + hv.z * wv.z + hv.w * wv.w;
    }

    float m = a;
#pragma unroll
    for (int o = 16; o; o >>= 1) m = fmaxf(m, __shfl_xor_sync(0xffffffffu, m, o));
    m = fmaxf(m, -999.0f);

    float ex = __expf(a - m);
    float ssum = ex;
#pragma unroll
    for (int o = 16; o; o >>= 1) ssum += __shfl_xor_sync(0xffffffffu, ssum, o);
    ssum += (float)(ASIZE - NPG) * __expf(-999.0f - m);
    float lse = __logf(ssum);

    out[warp * ASIZE + lane] = a - m - lse;
    if (lane < ASIZE - 32) out[warp * ASIZE + 32 + lane] = -999.0f - m - lse;
}

/* ---------------- launch ---------------- */
extern "C" void kernel_launch(void* const* d_in, const int* in_sizes, int n_in,
                              void* d_out, int out_size)
{
    const float* x       = (const float*)d_in[0];
    const float* src_num = (const float*)d_in[1];
    const float* tgt_num = (const float*)d_in[2];
    const int*   tokens  = (const int*)d_in[3];
    const int*   ei      = (const int*)d_in[4];
    /* d_in[5] = batch (structure known: i/32), unused */
    const float* emb  = (const float*)d_in[6];
    const float* wihf = (const float*)d_in[7];
    const float* whhf = (const float*)d_in[8];
    const float* bf   = (const float*)d_in[9];
    const float* wihb = (const float*)d_in[10];
    const float* whhb = (const float*)d_in[11];
    const float* bb   = (const float*)d_in[12];
    const float* p1w  = (const float*)d_in[13];
    const float* p1b  = (const float*)d_in[14];
    const float* p2w  = (const float*)d_in[15];
    const float* p2b  = (const float*)d_in[16];
    const float* p3w  = (const float*)d_in[17];
    const float* p3b  = (const float*)d_in[18];
    const float* p4w  = (const float*)d_in[19];
    const float* p4b  = (const float*)d_in[20];
    const float* v1w  = (const float*)d_in[21];
    const float* v1b  = (const float*)d_in[22];
    const float* v2w  = (const float*)d_in[23];
    const float* v2b  = (const float*)d_in[24];
    float* out = (float*)d_out;

    void *ph1 = 0, *ph2 = 0, *ph3 = 0;
    cudaGetSymbolAddress(&ph1, g_h1);
    cudaGetSymbolAddress(&ph2, g_h2);
    cudaGetSymbolAddress(&ph3, g_h3);

    k_prep<<<32, 256>>>(emb, wihf, whhf, bf, wihb, whhb, bb);
    k_zero<<<4096, 256>>>();
    k_lstm2<<<N_EDGES / 32, 128>>>(tokens);
    k_scatter<<<N_EDGES, 128>>>(ei, src_num, tgt_num);
    k_inv<<<N_NODES / 256, 256>>>();

    k_gemm1<<<N_NODES / 128, 256>>>(x, p1w, p1b, (float*)ph1);
    k_gemm<64, 128><<<N_NODES / 128, 128>>>((const float*)ph1, p2w, p2b, (float*)ph2,
                                            N_NODES, 64, 128, 1);
    k_gemm<32, 64><<<N_NODES / 128, 64>>>((const float*)ph2, p3w, p3b, (float*)ph3,
                                          N_NODES, 32, 64, 1);

    k_pool_value<<<NB, 128>>>(x, v1w, v1b, v2w, v2b, out);
    k_softmax<<<NB / 8, 256>>>(p4w, p4b, out);
}

// round 7
// speedup vs baseline: 3.4545x; 1.2146x over previous
#include <cuda_runtime.h>
#include <cuda_bf16.h>
#include <cuda_fp16.h>
#include <math.h>
#include <stdint.h>

#define N_NODES 131072
#define N_EDGES 65536
#define NB      4096
#define NPG     32
#define ASIZE   53
#define SD      53      /* STATE_DIM */
#define FEAT    117     /* 53 + 64 */
#define XDIM    55
#define XCDIM   289
#define TLEN    50

/* ---------------- scratch (device globals; no allocation allowed) ---------------- */
__device__ float4 g_Tf[660];                       /* gate table fwd: [v][33][4 gates i,f,g,o] */
__device__ float4 g_Tb[660];
__device__ __half g_Whh[2][32 * 128];              /* W_hh fp16-hi, col j=(h>>3)*32+g*8+(h&7) */
__device__ __half g_Wlh[2][32 * 128];              /* fp16 residual */
__device__ float  g_regex[N_EDGES * 64];
__device__ float  g_in_acc[N_NODES * FEAT];
__device__ float  g_out_acc[N_NODES * FEAT];
__device__ int    g_cnt_in[N_NODES];
__device__ int    g_cnt_out[N_NODES];
__device__ float  g_inv_in[N_NODES];
__device__ float  g_inv_out[N_NODES];
__device__ float  g_h1[(size_t)N_NODES * 128];
__device__ float  g_h2[(size_t)N_NODES * 64];
__device__ float  g_h3[(size_t)N_NODES * 32];

/* ---------------- helpers ---------------- */
__device__ __forceinline__ float tanhh(float x) {
    float y;
    asm("tanh.approx.f32 %0, %1;" : "=f"(y) : "f"(x));
    return y;
}
__device__ __forceinline__ float sigf(float x) {
    return fmaf(0.5f, tanhh(0.5f * x), 0.5f);
}
__device__ __forceinline__ uint32_t packh2(__half a, __half b) {
    __half2 h = __halves2half2(a, b);
    return *reinterpret_cast<uint32_t*>(&h);
}
/* split a float2 into fp16 hi pair + fp16 lo pair (packed b32 each) */
__device__ __forceinline__ void f2_split(float2 f, uint32_t& hi, uint32_t& lo) {
    __half2 h = __float22half2_rn(f);
    float2 r;
    r.x = f.x - __half2float(__low2half(h));
    r.y = f.y - __half2float(__high2half(h));
    __half2 l = __float22half2_rn(r);
    hi = *reinterpret_cast<uint32_t*>(&h);
    lo = *reinterpret_cast<uint32_t*>(&l);
}
#define MMA_F16(D, A, B) \
    asm volatile("mma.sync.aligned.m16n8k16.row.col.f32.f16.f16.f32 " \
        "{%0,%1,%2,%3}, {%4,%5,%6,%7}, {%8,%9}, {%0,%1,%2,%3};" \
        : "+f"((D)[0]), "+f"((D)[1]), "+f"((D)[2]), "+f"((D)[3]) \
        : "r"((A)[0]), "r"((A)[1]), "r"((A)[2]), "r"((A)[3]), \
          "r"((B)[0]), "r"((B)[1]))

/* fused xc element: [x | in_acc*inv | out_acc*inv] */
__device__ __forceinline__ float xc_elem(const float* __restrict__ x, int n, int f) {
    if (f < XDIM)        return x[n * XDIM + f];
    if (f < XDIM + FEAT) return g_in_acc[n * FEAT + (f - XDIM)] * g_inv_in[n];
    if (f < XCDIM)       return g_out_acc[n * FEAT + (f - XDIM - FEAT)] * g_inv_out[n];
    return 0.0f;
}

/* ---------------- prep: gate tables + W_hh fp16 split relayout ---------------- */
__global__ void k_prep(const float* __restrict__ emb,
                       const float* __restrict__ wihf, const float* __restrict__ whhf,
                       const float* __restrict__ bf,
                       const float* __restrict__ wihb, const float* __restrict__ whhb,
                       const float* __restrict__ bb)
{
    int tid = blockIdx.x * blockDim.x + threadIdx.x;
    /* T[dir][v][j] = b[j] + sum_k emb[v,k] * w_ih[j,k]; 2 x 20 x 128 */
    if (tid < 5120) {
        int dir = tid / 2560, r = tid % 2560, v = r >> 7, j = r & 127;
        const float* wih = dir ? wihb : wihf;
        const float* b   = dir ? bb   : bf;
        float s = b[j];
#pragma unroll
        for (int k = 0; k < 8; ++k) s = fmaf(emb[v * 8 + k], wih[j * 8 + k], s);
        int l = j & 31, g = j >> 5;
        ((float*)(dir ? g_Tb : g_Tf))[v * 132 + l * 4 + g] = s;
    }
    /* W relayout: col j = (h>>3)*32 + gate*8 + (h&7); W[m][j] = w_hh[gate*32+h][m] */
    if (tid < 8192) {
        int dir = tid >> 12, r = tid & 4095, m = r >> 7, j = r & 127;
        int wg = j >> 5, g = (j >> 3) & 3, hl = j & 7;
        int h = wg * 8 + hl;
        const float* whh = dir ? whhb : whhf;
        float v = whh[(g * 32 + h) * 32 + m];
        __half hi = __float2half_rn(v);
        __half lo = __float2half_rn(v - __half2float(hi));
        g_Whh[dir][m * 128 + j] = hi;
        g_Wlh[dir][m * 128 + j] = lo;
    }
}

/* ---------------- zero accumulators ---------------- */
__global__ void k_zero()
{
    int stride = gridDim.x * blockDim.x;
    int t0 = blockIdx.x * blockDim.x + threadIdx.x;
    for (int i = t0; i < N_NODES * FEAT; i += stride) {
        g_in_acc[i]  = 0.0f;
        g_out_acc[i] = 0.0f;
    }
    for (int i = t0; i < N_NODES; i += stride) {
        g_cnt_in[i]  = 0;
        g_cnt_out[i] = 0;
    }
}

/* ---------------- reciprocal counts (after scatter) ---------------- */
__global__ void k_inv()
{
    int n = blockIdx.x * blockDim.x + threadIdx.x;
    if (n < N_NODES) {
        g_inv_in[n]  = 1.0f / fmaxf((float)g_cnt_in[n], 1.0f);
        g_inv_out[n] = 1.0f / fmaxf((float)g_cnt_out[n], 1.0f);
    }
}

/* ---------------- bidirectional LSTM via fp16 tensor cores ----------------
   Block = 32 edges, 4 warps. Each step: Z[32,128] = T[tok] + H[32,32]@W[32,128]
   with 3-term fp16 split mma (m16n8k16, ~fp32 accuracy). W in B-fragments.
   Double-buffered H, one barrier per step. */
__global__ void __launch_bounds__(128) k_lstm2(const int* __restrict__ tokens)
{
    __shared__ float4 sT[660];          /* token gate table (per dir) */
    __shared__ float  sH[2][32][36];    /* h state, double-buffered */
    __shared__ int    sTok[32 * TLEN];

    int tid = threadIdx.x;
    int w = tid >> 5, lane = tid & 31;
    int q = lane & 3, r = lane >> 2;
    int e0 = blockIdx.x * 32;
    int hcol = w * 8 + 2 * q;           /* this thread's hidden pair base */

    for (int i = tid; i < 32 * TLEN; i += 128) sTok[i] = tokens[e0 * TLEN + i];

    for (int dir = 0; dir < 2; ++dir) {
        __syncthreads();
        const float4* gT = dir ? g_Tb : g_Tf;
        for (int i = tid; i < 660; i += 128) sT[i] = gT[i];
        for (int i = tid; i < 2 * 32 * 36; i += 128) ((float*)sH)[i] = 0.0f;

        /* B fragments: [ktile][gate][reg], in registers for the whole pass.
           b0: k = k0+2q, k0+2q+1 ; b1: k = k0+2q+8, k0+2q+9 ; n = w*32+g*8+r */
        uint32_t bhi[2][2][4][2], blo_[2][2][4][2];  /* [unused dim folded below] */
        uint32_t (*bh)[4][2] = bhi[0];
        uint32_t (*bl)[4][2] = blo_[0];
        const __half* Wh = g_Whh[dir];
        const __half* Wl = g_Wlh[dir];
#pragma unroll
        for (int kt = 0; kt < 2; ++kt)
#pragma unroll
            for (int g = 0; g < 4; ++g) {
                int n = w * 32 + g * 8 + r;
                int k0 = kt * 16;
                bh[kt][g][0] = packh2(Wh[(k0 + 2 * q) * 128 + n],     Wh[(k0 + 2 * q + 1) * 128 + n]);
                bh[kt][g][1] = packh2(Wh[(k0 + 2 * q + 8) * 128 + n], Wh[(k0 + 2 * q + 9) * 128 + n]);
                bl[kt][g][0] = packh2(Wl[(k0 + 2 * q) * 128 + n],     Wl[(k0 + 2 * q + 1) * 128 + n]);
                bl[kt][g][1] = packh2(Wl[(k0 + 2 * q + 8) * 128 + n], Wl[(k0 + 2 * q + 9) * 128 + n]);
            }

        float cst[8], acc[8];
#pragma unroll
        for (int p = 0; p < 8; ++p) { cst[p] = 0.0f; acc[p] = 0.0f; }

        __syncthreads();

        int pb = 0;
        for (int t = 0; t < TLEN; ++t) {
            int tt = dir ? (TLEN - 1 - t) : t;

            /* D init = token gate biases (exact fp32 input contribution) */
            float d[2][4][4];   /* [mt][gate][rh*2+b] */
#pragma unroll
            for (int mt = 0; mt < 2; ++mt)
#pragma unroll
                for (int rh = 0; rh < 2; ++rh) {
                    int edge = mt * 16 + rh * 8 + r;
                    int tk = sTok[edge * TLEN + tt];
                    float4 t0 = sT[tk * 33 + hcol];
                    float4 t1 = sT[tk * 33 + hcol + 1];
                    d[mt][0][rh * 2 + 0] = t0.x; d[mt][1][rh * 2 + 0] = t0.y;
                    d[mt][2][rh * 2 + 0] = t0.z; d[mt][3][rh * 2 + 0] = t0.w;
                    d[mt][0][rh * 2 + 1] = t1.x; d[mt][1][rh * 2 + 1] = t1.y;
                    d[mt][2][rh * 2 + 1] = t1.z; d[mt][3][rh * 2 + 1] = t1.w;
                }

            /* Z += H @ W via 3-term fp16 split mma (m16n8k16) */
#pragma unroll
            for (int kt = 0; kt < 2; ++kt) {
                int k0 = kt * 16;
                uint32_t ahi[2][4], alo[2][4];
#pragma unroll
                for (int mt = 0; mt < 2; ++mt) {
                    float2 f00 = *(const float2*)&sH[pb][mt * 16 + r][k0 + 2 * q];
                    float2 f10 = *(const float2*)&sH[pb][mt * 16 + r + 8][k0 + 2 * q];
                    float2 f01 = *(const float2*)&sH[pb][mt * 16 + r][k0 + 2 * q + 8];
                    float2 f11 = *(const float2*)&sH[pb][mt * 16 + r + 8][k0 + 2 * q + 8];
                    f2_split(f00, ahi[mt][0], alo[mt][0]);
                    f2_split(f10, ahi[mt][1], alo[mt][1]);
                    f2_split(f01, ahi[mt][2], alo[mt][2]);
                    f2_split(f11, ahi[mt][3], alo[mt][3]);
                }
#pragma unroll
                for (int mt = 0; mt < 2; ++mt)
#pragma unroll
                    for (int g = 0; g < 4; ++g) {
                        MMA_F16(d[mt][g], ahi[mt], bh[kt][g]);
                        MMA_F16(d[mt][g], alo[mt], bh[kt][g]);
                        MMA_F16(d[mt][g], ahi[mt], bl[kt][g]);
                    }
            }

            /* elementwise gates on registers; write new h into other buffer */
#pragma unroll
            for (int mt = 0; mt < 2; ++mt)
#pragma unroll
                for (int rh = 0; rh < 2; ++rh)
#pragma unroll
                    for (int b = 0; b < 2; ++b) {
                        int p = mt * 4 + rh * 2 + b;
                        int reg = rh * 2 + b;
                        float zi = d[mt][0][reg], zf = d[mt][1][reg];
                        float zg = d[mt][2][reg], zo = d[mt][3][reg];
                        float cn = sigf(zf) * cst[p] + sigf(zi) * tanhh(zg);
                        float h = sigf(zo) * tanhh(cn);
                        cst[p] = cn;
                        acc[p] += h;
                        sH[pb ^ 1][mt * 16 + rh * 8 + r][hcol + b] = h;
                    }
            __syncthreads();
            pb ^= 1;
        }

#pragma unroll
        for (int mt = 0; mt < 2; ++mt)
#pragma unroll
            for (int rh = 0; rh < 2; ++rh)
#pragma unroll
                for (int b = 0; b < 2; ++b) {
                    int p = mt * 4 + rh * 2 + b;
                    int edge = e0 + mt * 16 + rh * 8 + r;
                    g_regex[edge * 64 + dir * 32 + hcol + b] = acc[p] * (1.0f / TLEN);
                }
    }
}

/* ---------------- edge scatter (segment sums via atomics) ---------------- */
__global__ void __launch_bounds__(128) k_scatter(const int* __restrict__ ei,
                                                 const float* __restrict__ src_num,
                                                 const float* __restrict__ tgt_num)
{
    int e = blockIdx.x;
    int f = threadIdx.x;
    int src = ei[e], tgt = ei[N_EDGES + e];
    if (f == 0) {
        atomicAdd(&g_cnt_out[src], 1);
        atomicAdd(&g_cnt_in[tgt], 1);
    }
    if (f < SD) {
        atomicAdd(&g_out_acc[src * FEAT + f], tgt_num[(size_t)e * SD + f]);
        atomicAdd(&g_in_acc[tgt * FEAT + f],  src_num[(size_t)e * SD + f]);
    } else if (f < FEAT) {
        float rf = g_regex[e * 64 + (f - SD)];
        atomicAdd(&g_out_acc[src * FEAT + f], rf);
        atomicAdd(&g_in_acc[tgt * FEAT + f],  rf);
    }
}

/* ---------------- gemm1: fused-A SGEMM  C = relu(xc @ p1w + b) ---------------- */
__global__ void __launch_bounds__(256) k_gemm1(const float* __restrict__ x,
                                               const float* __restrict__ B,
                                               const float* __restrict__ bias,
                                               float* __restrict__ C)
{
    constexpr int BM = 128, BN = 128, BK = 16, TM = 8, TN = 8, NT = 256;
    constexpr int NX = BN / TN;
    constexpr int K = XCDIM, N = BN;
    __shared__ float As[BK][BM + 1];
    __shared__ float Bs[BK][BN];

    int tid = threadIdx.x;
    int tx = tid % NX, ty = tid / NX;
    int bm = blockIdx.x * BM;

    float acc[TM][TN];
#pragma unroll
    for (int i = 0; i < TM; ++i)
#pragma unroll
        for (int j = 0; j < TN; ++j) acc[i][j] = 0.0f;

    int nk = (K + BK - 1) / BK;
    for (int kc = 0; kc < nk; ++kc) {
        int k0 = kc * BK;
        for (int e = tid; e < BM * BK; e += NT) {
            int m = e / BK, k = e % BK;
            As[k][m] = xc_elem(x, bm + m, k0 + k);
        }
        for (int e = tid * 4; e < BK * BN; e += NT * 4) {
            int k = e / BN, n = e % BN;
            float4 v = make_float4(0.f, 0.f, 0.f, 0.f);
            if (k0 + k < K) v = *(const float4*)(B + (k0 + k) * N + n);
            *(float4*)(&Bs[k][n]) = v;
        }
        __syncthreads();
#pragma unroll
        for (int kk = 0; kk < BK; ++kk) {
            float a[TM], b[TN];
#pragma unroll
            for (int i = 0; i < TM; ++i) a[i] = As[kk][ty * TM + i];
#pragma unroll
            for (int j = 0; j < TN; ++j) b[j] = Bs[kk][tx * TN + j];
#pragma unroll
            for (int i = 0; i < TM; ++i)
#pragma unroll
                for (int j = 0; j < TN; ++j) acc[i][j] = fmaf(a[i], b[j], acc[i][j]);
        }
        __syncthreads();
    }
#pragma unroll
    for (int i = 0; i < TM; ++i) {
        int m = bm + ty * TM + i;
#pragma unroll
        for (int j = 0; j < TN; j += 4) {
            int n = tx * TN + j;
            float4 v;
            v.x = fmaxf(acc[i][j + 0] + bias[n + 0], 0.f);
            v.y = fmaxf(acc[i][j + 1] + bias[n + 1], 0.f);
            v.z = fmaxf(acc[i][j + 2] + bias[n + 2], 0.f);
            v.w = fmaxf(acc[i][j + 3] + bias[n + 3], 0.f);
            *(float4*)(C + (size_t)m * N + n) = v;
        }
    }
}

/* ---------------- tiled SGEMM + bias + relu (gemm2/3) ---------------- */
template <int BN, int NT>
__global__ void __launch_bounds__(NT) k_gemm(const float* __restrict__ A,
                                             const float* __restrict__ B,
                                             const float* __restrict__ bias,
                                             float* __restrict__ C,
                                             int M, int N, int K, int doRelu)
{
    constexpr int BM = 128, BK = 16, TM = 8, TN = 8;
    constexpr int NX = BN / TN;
    __shared__ float As[BK][BM + 1];
    __shared__ float Bs[BK][BN];

    int tid = threadIdx.x;
    int tx = tid % NX, ty = tid / NX;
    int bm = blockIdx.x * BM;

    float acc[TM][TN];
#pragma unroll
    for (int i = 0; i < TM; ++i)
#pragma unroll
        for (int j = 0; j < TN; ++j) acc[i][j] = 0.0f;

    int nk = (K + BK - 1) / BK;
    for (int kc = 0; kc < nk; ++kc) {
        int k0 = kc * BK;
        for (int e = tid; e < BM * BK; e += NT) {
            int m = e / BK, k = e % BK;
            As[k][m] = (k0 + k < K) ? A[(bm + m) * K + k0 + k] : 0.0f;
        }
        for (int e = tid * 4; e < BK * BN; e += NT * 4) {
            int k = e / BN, n = e % BN;
            float4 v = make_float4(0.f, 0.f, 0.f, 0.f);
            if (k0 + k < K) v = *(const float4*)(B + (k0 + k) * N + n);
            *(float4*)(&Bs[k][n]) = v;
        }
        __syncthreads();
#pragma unroll
        for (int kk = 0; kk < BK; ++kk) {
            float a[TM], b[TN];
#pragma unroll
            for (int i = 0; i < TM; ++i) a[i] = As[kk][ty * TM + i];
#pragma unroll
            for (int j = 0; j < TN; ++j) b[j] = Bs[kk][tx * TN + j];
#pragma unroll
            for (int i = 0; i < TM; ++i)
#pragma unroll
                for (int j = 0; j < TN; ++j) acc[i][j] = fmaf(a[i], b[j], acc[i][j]);
        }
        __syncthreads();
    }
#pragma unroll
    for (int i = 0; i < TM; ++i) {
        int m = bm + ty * TM + i;
#pragma unroll
        for (int j = 0; j < TN; j += 4) {
            int n = tx * TN + j;
            float4 v;
            v.x = acc[i][j + 0] + bias[n + 0];
            v.y = acc[i][j + 1] + bias[n + 1];
            v.z = acc[i][j + 2] + bias[n + 2];
            v.w = acc[i][j + 3] + bias[n + 3];
            if (doRelu) {
                v.x = fmaxf(v.x, 0.f); v.y = fmaxf(v.y, 0.f);
                v.z = fmaxf(v.z, 0.f); v.w = fmaxf(v.w, 0.f);
            }
            *(float4*)(C + (size_t)m * N + n) = v;
        }
    }
}

/* ---------------- graph mean pool + value head (fused xc) ---------------- */
__global__ void __launch_bounds__(128) k_pool_value(const float* __restrict__ x,
                                                    const float* __restrict__ v1w,
                                                    const float* __restrict__ v1b,
                                                    const float* __restrict__ v2w,
                                                    const float* __restrict__ v2b,
                                                    float* __restrict__ out)
{
    __shared__ float s[XCDIM];
    int g = blockIdx.x;
    for (int f = threadIdx.x; f < XCDIM; f += 128) {
        float sum = 0.0f;
#pragma unroll 4
        for (int i = 0; i < NPG; ++i) sum += xc_elem(x, g * NPG + i, f);
        s[f] = sum * (1.0f / NPG);
    }
    __syncthreads();
    if (threadIdx.x < 32) {
        int j = threadIdx.x;
        float a = v1b[j];
        for (int i = 0; i < XCDIM; ++i) a = fmaf(s[i], v1w[i * 32 + j], a);
        float hv = fmaxf(a, 0.0f) * v2w[j];
#pragma unroll
        for (int o = 16; o; o >>= 1) hv += __shfl_xor_sync(0xffffffffu, hv, o);
        if (j == 0) out[NB * ASIZE + g] = hv + v2b[0];
    }
}

/* ---------------- pi head (32->1) + ragged pack + log_softmax ---------------- */
__global__ void k_softmax(const float* __restrict__ p4w, const float* __restrict__ p4b,
                          float* __restrict__ out)
{
    int warp = (blockIdx.x * blockDim.x + threadIdx.x) >> 5;
    int lane = threadIdx.x & 31;
    if (warp >= NB) return;
    int node = warp * NPG + lane;

    const float4* h3 = (const float4*)(g_h3 + (size_t)node * 32);
    const float4* w4 = (const float4*)p4w;
    float a = p4b[0];
#pragma unroll
    for (int qq = 0; qq < 8; ++qq) {
        float4 hv = h3[qq];
        float4 wv = w4[qq];
        a += hv.x * wv.x + hv.y * wv.y + hv.z * wv.z + hv.w * wv.w;
    }

    float m = a;
#pragma unroll
    for (int o = 16; o; o >>= 1) m = fmaxf(m, __shfl_xor_sync(0xffffffffu, m, o));
    m = fmaxf(m, -999.0f);

    float ex = __expf(a - m);
    float ssum = ex;
#pragma unroll
    for (int o = 16; o; o >>= 1) ssum += __shfl_xor_sync(0xffffffffu, ssum, o);
    ssum += (float)(ASIZE - NPG) * __expf(-999.0f - m);
    float lse = __logf(ssum);

    out[warp * ASIZE + lane] = a - m - lse;
    if (lane < ASIZE - 32) out[warp * ASIZE + 32 + lane] = -999.0f - m - lse;
}

/* ---------------- launch ---------------- */
extern "C" void kernel_launch(void* const* d_in, const int* in_sizes, int n_in,
                              void* d_out, int out_size)
{
    const float* x       = (const float*)d_in[0];
    const float* src_num = (const float*)d_in[1];
    const float* tgt_num = (const float*)d_in[2];
    const int*   tokens  = (const int*)d_in[3];
    const int*   ei      = (const int*)d_in[4];
    /* d_in[5] = batch (structure known: i/32), unused */
    const float* emb  = (const float*)d_in[6];
    const float* wihf = (const float*)d_in[7];
    const float* whhf = (const float*)d_in[8];
    const float* bf   = (const float*)d_in[9];
    const float* wihb = (const float*)d_in[10];
    const float* whhb = (const float*)d_in[11];
    const float* bb   = (const float*)d_in[12];
    const float* p1w  = (const float*)d_in[13];
    const float* p1b  = (const float*)d_in[14];
    const float* p2w  = (const float*)d_in[15];
    const float* p2b  = (const float*)d_in[16];
    const float* p3w  = (const float*)d_in[17];
    const float* p3b  = (const float*)d_in[18];
    const float* p4w  = (const float*)d_in[19];
    const float* p4b  = (const float*)d_in[20];
    const float* v1w  = (const float*)d_in[21];
    const float* v1b  = (const float*)d_in[22];
    const float* v2w  = (const float*)d_in[23];
    const float* v2b  = (const float*)d_in[24];
    float* out = (float*)d_out;

    void *ph1 = 0, *ph2 = 0, *ph3 = 0;
    cudaGetSymbolAddress(&ph1, g_h1);
    cudaGetSymbolAddress(&ph2, g_h2);
    cudaGetSymbolAddress(&ph3, g_h3);

    k_prep<<<32, 256>>>(emb, wihf, whhf, bf, wihb, whhb, bb);
    k_zero<<<4096, 256>>>();
    k_lstm2<<<N_EDGES / 32, 128>>>(tokens);
    k_scatter<<<N_EDGES, 128>>>(ei, src_num, tgt_num);
    k_inv<<<N_NODES / 256, 256>>>();

    k_gemm1<<<N_NODES / 128, 256>>>(x, p1w, p1b, (float*)ph1);
    k_gemm<64, 128><<<N_NODES / 128, 128>>>((const float*)ph1, p2w, p2b, (float*)ph2,
                                            N_NODES, 64, 128, 1);
    k_gemm<32, 64><<<N_NODES / 128, 64>>>((const float*)ph2, p3w, p3b, (float*)ph3,
                                          N_NODES, 32, 64, 1);

    k_pool_value<<<NB, 128>>>(x, v1w, v1b, v2w, v2b, out);
    k_softmax<<<NB / 8, 256>>>(p4w, p4b, out);
}